// round 15
// baseline (speedup 1.0000x reference)
#include <cuda_runtime.h>
#include <math.h>

#define C_IN 768
#define DDIM 8
#define LDIM 8

#define THREADS 256
#define TILE 64                 // tokens per block (oct handles 2 tokens)
#define HALF 32                 // t1 = t0 + HALF
#define NITER (C_IN / 32)       // 24 chunks, 4 floats per lane per chunk
#define EXP_THREADS 192         // phase-2 channel owners (192*4 = 768)

// Scratch (no allocations allowed)
__device__ float g_partials[1024];
__device__ unsigned int g_done = 0;   // self-resetting via atomicInc wrap

static __device__ __forceinline__ unsigned long long pack2(float lo, float hi) {
    unsigned long long r;
    asm("mov.b64 %0, {%1, %2};" : "=l"(r) : "f"(lo), "f"(hi));
    return r;
}
static __device__ __forceinline__ void unpack2(unsigned long long v, float& lo, float& hi) {
    asm("mov.b64 {%0, %1}, %2;" : "=f"(lo), "=f"(hi) : "l"(v));
}
// Packed fp32x2 FMA (sm_100+): 2 IEEE fp32 FMAs per instruction.
static __device__ __forceinline__ unsigned long long fma2(unsigned long long a,
                                                          unsigned long long b,
                                                          unsigned long long c) {
    unsigned long long d;
    asm("fma.rn.f32x2 %0, %1, %2, %3;" : "=l"(d) : "l"(a), "l"(b), "l"(c));
    return d;
}

// Fused kernel:
//   Phase 1: compress GEMV with 8 lanes/token (chunk = one full 128B line of z
//            -> 4 L1 wavefronts per warp-LDG instead of 8) and 2 tokens per
//            oct (weight LDS reuse). 24 chunks, barrier-free. Gumbel argmax
//            (lane o owns dim o); codes -> shared, error partial -> global.
//   Phase 2: expand z_q = codes @ We + be from shared, coalesced STG.128.
//   Tail:    deterministic last-block reduction of error partials.
__global__ void __launch_bounds__(THREADS, 4) k_fused(
    const float* __restrict__ z, const float* __restrict__ u,
    const float* __restrict__ Wc, const float* __restrict__ bc,
    const float* __restrict__ We, const float* __restrict__ be,
    const float* __restrict__ cb,
    float* __restrict__ out, int ntok, int nblk,
    long long erridx, float errinv)
{
    __shared__ __align__(128) float sWcT[DDIM * C_IN];           // 24 KB transposed
    __shared__ __align__(16) unsigned long long sC[TILE * DDIM]; // 4 KB (code,code)
    __shared__ float sBC[DDIM];
    __shared__ float sCB[DDIM * LDIM];
    __shared__ float sRed[THREADS / 32];
    __shared__ unsigned int sLast;

    const int tid = threadIdx.x;

    // Stage transposed compress weights (coalesced global reads; L2-resident)
    for (int i = tid; i < C_IN * DDIM; i += THREADS) {
        int c = i >> 3, d = i & 7;
        sWcT[d * C_IN + c] = Wc[i];
    }
    if (tid < DDIM) sBC[tid] = bc[tid];
    if (tid < DDIM * LDIM) sCB[tid] = cb[tid];
    __syncthreads();

    // ---------------- Phase 1: compress (2 tokens per oct) ----------------
    const int o8 = tid & 7;                        // lane within oct
    const int trow = tid >> 3;                     // 0..31 token slot
    const int tokA = blockIdx.x * TILE + trow;     // first token
    const int tokB = tokA + HALF;                  // second token
    const int lA = (tokA < ntok) ? tokA : (ntok - 1);
    const int lB = (tokB < ntok) ? tokB : (ntok - 1);
    const float* zrowA = z + (size_t)lA * C_IN + 4 * o8;
    const float* zrowB = z + (size_t)lB * C_IN + 4 * o8;

    unsigned long long accA[DDIM], accB[DDIM];
    #pragma unroll
    for (int d = 0; d < DDIM; d++) { accA[d] = pack2(0.f, 0.f); accB[d] = accA[d]; }

    // Mainloop: per chunk, each token's 32 floats = one aligned 128B line.
    // unroll-4 lets ptxas front-batch the LDG.128s.
    #pragma unroll 4
    for (int k = 0; k < NITER; k++) {
        float4 av = *reinterpret_cast<const float4*>(zrowA + 32 * k);
        float4 bv = *reinterpret_cast<const float4*>(zrowB + 32 * k);
        unsigned long long zpa01 = pack2(av.x, av.y);
        unsigned long long zpa23 = pack2(av.z, av.w);
        unsigned long long zpb01 = pack2(bv.x, bv.y);
        unsigned long long zpb23 = pack2(bv.z, bv.w);
        const float* wbase = sWcT + 32 * k + 4 * o8;
        #pragma unroll
        for (int d = 0; d < DDIM; d++) {
            ulonglong2 wd = *reinterpret_cast<const ulonglong2*>(wbase + d * C_IN);
            accA[d] = fma2(zpa01, wd.x, accA[d]);
            accA[d] = fma2(zpa23, wd.y, accA[d]);
            accB[d] = fma2(zpb01, wd.x, accB[d]);
            accB[d] = fma2(zpb23, wd.y, accB[d]);
        }
    }

    // Reduce across the 8 lanes of the oct; lane o keeps dim o (both tokens)
    float zcA = 0.f, zcB = 0.f;
    #pragma unroll
    for (int d = 0; d < DDIM; d++) {
        float lo, hi, va, vb;
        unpack2(accA[d], lo, hi); va = lo + hi;
        unpack2(accB[d], lo, hi); vb = lo + hi;
        va += __shfl_xor_sync(0xffffffffu, va, 1);
        va += __shfl_xor_sync(0xffffffffu, va, 2);
        va += __shfl_xor_sync(0xffffffffu, va, 4);
        vb += __shfl_xor_sync(0xffffffffu, vb, 1);
        vb += __shfl_xor_sync(0xffffffffu, vb, 2);
        vb += __shfl_xor_sync(0xffffffffu, vb, 4);
        float bcv = sBC[d];
        if (d == o8) { zcA = va + bcv; zcB = vb + bcv; }
    }

    // Argmax per token; lane o owns dim o. u row: floats [8*o, 8*o+8)
    float err = 0.0f;
    #pragma unroll
    for (int half = 0; half < 2; half++) {
        const int mtok = half ? tokB : tokA;
        const int lt   = half ? lB : lA;
        const float zv = half ? zcB : zcA;
        const float4* u4 = reinterpret_cast<const float4*>(
            u + (size_t)lt * (DDIM * LDIM) + 8 * o8);
        float4 ua = u4[0], ub = u4[1];
        float uv[LDIM] = {ua.x, ua.y, ua.z, ua.w, ub.x, ub.y, ub.z, ub.w};

        // argmax_l of gumbel(u) - |zc - cb| (== reference softmax argmax,
        // TAU=1; strict > keeps first index on ties, matching jnp.argmax)
        float best = -INFINITY;
        float code = 0.f;
        #pragma unroll
        for (int l = 0; l < LDIM; l++) {
            float cbv = sCB[o8 * LDIM + l];
            float g = -logf(-logf(uv[l] + 1e-10f));
            float s = g - fabsf(zv - cbv);
            if (s > best) { best = s; code = cbv; }
        }
        if (mtok < ntok) {
            float e = zv - code;
            err += e * e;
        }
        sC[(trow + half * HALF) * DDIM + o8] = pack2(code, code);
    }

    // Block-reduce squared error -> per-block partial
    #pragma unroll
    for (int o = 16; o > 0; o >>= 1) err += __shfl_down_sync(0xffffffffu, err, o);
    if ((tid & 31) == 0) sRed[tid >> 5] = err;
    __syncthreads();   // also publishes sC for phase 2
    if (tid == 0) {
        float t = 0.f;
        #pragma unroll
        for (int w = 0; w < THREADS / 32; w++) t += sRed[w];
        g_partials[blockIdx.x] = t;
    }

    // ---------------- Phase 2: expand ----------------
    if (tid < EXP_THREADS) {
        const int c0 = tid * 4;
        ulonglong2 wv[DDIM];
        #pragma unroll
        for (int d = 0; d < DDIM; d++)
            wv[d] = *reinterpret_cast<const ulonglong2*>(&We[d * C_IN + c0]);
        ulonglong2 bev = *reinterpret_cast<const ulonglong2*>(&be[c0]);

        const int tok0 = blockIdx.x * TILE;
        int tmax = ntok - tok0;
        if (tmax > TILE) tmax = TILE;

        int t = 0;
        for (; t + 4 <= tmax; t += 4) {
            unsigned long long a[4][2];
            #pragma unroll
            for (int q = 0; q < 4; q++) { a[q][0] = bev.x; a[q][1] = bev.y; }
            #pragma unroll
            for (int d = 0; d < DDIM; d++) {
                #pragma unroll
                for (int q = 0; q < 4; q++) {
                    unsigned long long cd = sC[(t + q) * DDIM + d];  // broadcast
                    a[q][0] = fma2(cd, wv[d].x, a[q][0]);
                    a[q][1] = fma2(cd, wv[d].y, a[q][1]);
                }
            }
            #pragma unroll
            for (int q = 0; q < 4; q++) {
                float4 ov;
                unpack2(a[q][0], ov.x, ov.y);
                unpack2(a[q][1], ov.z, ov.w);
                *reinterpret_cast<float4*>(
                    &out[(size_t)(tok0 + t + q) * C_IN + c0]) = ov;
            }
        }
        for (; t < tmax; t++) {
            unsigned long long s0 = bev.x, s1 = bev.y;
            #pragma unroll
            for (int d = 0; d < DDIM; d++) {
                unsigned long long cd = sC[t * DDIM + d];
                s0 = fma2(cd, wv[d].x, s0);
                s1 = fma2(cd, wv[d].y, s1);
            }
            float4 ov;
            unpack2(s0, ov.x, ov.y);
            unpack2(s1, ov.z, ov.w);
            *reinterpret_cast<float4*>(&out[(size_t)(tok0 + t) * C_IN + c0]) = ov;
        }
    }

    // ---------------- Tail: last block finalizes the error scalar ----------
    if (erridx >= 0) {
        if (tid == 0) {
            __threadfence();  // publish g_partials[bid] before counting
            // wraps to 0 after nblk increments -> self-resetting across replays
            sLast = (atomicInc(&g_done, (unsigned)nblk - 1u) == (unsigned)nblk - 1u);
        }
        __syncthreads();
        if (sLast) {
            float s = 0.f;
            for (int i = tid; i < nblk; i += THREADS) s += g_partials[i];
            #pragma unroll
            for (int o = 16; o > 0; o >>= 1)
                s += __shfl_down_sync(0xffffffffu, s, o);
            if ((tid & 31) == 0) sRed[tid >> 5] = s;
            __syncthreads();
            if (tid == 0) {
                float tot = 0.f;
                #pragma unroll
                for (int w = 0; w < THREADS / 32; w++) tot += sRed[w];
                out[erridx] = tot * errinv;
            }
        }
    }
}

extern "C" void kernel_launch(void* const* d_in, const int* in_sizes, int n_in,
                              void* d_out, int out_size) {
    const float* z  = (const float*)d_in[0];
    const float* u  = (const float*)d_in[1];
    const float* Wc = (const float*)d_in[2];
    const float* bc = (const float*)d_in[3];
    const float* We = (const float*)d_in[4];
    const float* be = (const float*)d_in[5];
    const float* cb = (const float*)d_in[6];
    // d_in[7] = codebook_mask: all-true here (levels == [8]*8), intentionally unused.
    float* out = (float*)d_out;

    const int ntok = in_sizes[0] / C_IN;            // 65536
    const int nblk = (ntok + TILE - 1) / TILE;      // 1024

    long long erridx = (out_size > ntok * C_IN) ? (long long)ntok * C_IN : -1;

    k_fused<<<nblk, THREADS>>>(z, u, Wc, bc, We, be, cb, out, ntok, nblk,
                               erridx, 1.0f / ((float)ntok * (float)DDIM));
}

// round 16
// speedup vs baseline: 1.1098x; 1.1098x over previous
#include <cuda_runtime.h>
#include <math.h>

#define C_IN 768
#define DDIM 8
#define LDIM 8

#define THREADS 256
#define TILE 128                // tokens per block (quad handles 2 tokens)
#define HALF 64                 // t1 = t0 + HALF
#define NITER (C_IN / 16)       // 48 chunks, 4 floats per lane per chunk
#define EXP_THREADS 192         // phase-2 channel owners (192*4 = 768)

// Scratch (no allocations allowed)
__device__ float g_partials[2048];
__device__ unsigned int g_done = 0;   // self-resetting via atomicInc wrap

static __device__ __forceinline__ unsigned long long pack2(float lo, float hi) {
    unsigned long long r;
    asm("mov.b64 %0, {%1, %2};" : "=l"(r) : "f"(lo), "f"(hi));
    return r;
}
static __device__ __forceinline__ void unpack2(unsigned long long v, float& lo, float& hi) {
    asm("mov.b64 {%0, %1}, %2;" : "=f"(lo), "=f"(hi) : "l"(v));
}
// Packed fp32x2 FMA (sm_100+): 2 IEEE fp32 FMAs per instruction.
static __device__ __forceinline__ unsigned long long fma2(unsigned long long a,
                                                          unsigned long long b,
                                                          unsigned long long c) {
    unsigned long long d;
    asm("fma.rn.f32x2 %0, %1, %2, %3;" : "=l"(d) : "l"(a), "l"(b), "l"(c));
    return d;
}
// Streaming (evict-first) 128-bit load/store for read-once / write-once data.
static __device__ __forceinline__ float4 ldcs4(const float4* p) {
    float4 v;
    asm volatile("ld.global.cs.v4.f32 {%0,%1,%2,%3}, [%4];"
                 : "=f"(v.x), "=f"(v.y), "=f"(v.z), "=f"(v.w) : "l"(p));
    return v;
}
static __device__ __forceinline__ void stcs4(float4* p, float4 v) {
    asm volatile("st.global.cs.v4.f32 [%0], {%1,%2,%3,%4};"
                 :: "l"(p), "f"(v.x), "f"(v.y), "f"(v.z), "f"(v.w) : "memory");
}

// Fused kernel (R13 champion shape + unroll-8 + streaming cache hints):
//   Phase 1: compress GEMV, 4 lanes/token, 2 tokens per quad (weight LDS
//            reuse). unroll-8 mainloop -> ptxas front-batches up to 16
//            LDG.128/thread. Gumbel argmax; codes -> shared.
//   Phase 2: expand z_q = codes @ We + be from shared, coalesced STG.128.
//   Tail:    deterministic last-block reduction of error partials.
__global__ void __launch_bounds__(THREADS, 4) k_fused(
    const float* __restrict__ z, const float* __restrict__ u,
    const float* __restrict__ Wc, const float* __restrict__ bc,
    const float* __restrict__ We, const float* __restrict__ be,
    const float* __restrict__ cb,
    float* __restrict__ out, int ntok, int nblk,
    long long erridx, float errinv)
{
    __shared__ __align__(16) float sWcT[DDIM * C_IN];            // 24 KB transposed
    __shared__ __align__(16) unsigned long long sC[TILE * DDIM]; // 8 KB (code,code)
    __shared__ float sBC[DDIM];
    __shared__ float sCB[DDIM * LDIM];
    __shared__ float sRed[THREADS / 32];
    __shared__ unsigned int sLast;

    const int tid = threadIdx.x;

    // Stage transposed compress weights (coalesced global reads)
    for (int i = tid; i < C_IN * DDIM; i += THREADS) {
        int c = i >> 3, d = i & 7;
        sWcT[d * C_IN + c] = Wc[i];
    }
    if (tid < DDIM) sBC[tid] = bc[tid];
    if (tid < DDIM * LDIM) sCB[tid] = cb[tid];
    __syncthreads();

    // ---------------- Phase 1: compress (2 tokens per quad) ----------------
    const int j = tid & 3;                         // lane within quad
    const int trow = tid >> 2;                     // 0..63
    const int tokA = blockIdx.x * TILE + trow;     // first token
    const int tokB = tokA + HALF;                  // second token
    const int lA = (tokA < ntok) ? tokA : (ntok - 1);
    const int lB = (tokB < ntok) ? tokB : (ntok - 1);
    const float* zrowA = z + (size_t)lA * C_IN + 4 * j;
    const float* zrowB = z + (size_t)lB * C_IN + 4 * j;

    unsigned long long accA[DDIM], accB[DDIM];
    #pragma unroll
    for (int d = 0; d < DDIM; d++) { accA[d] = pack2(0.f, 0.f); accB[d] = accA[d]; }

    // Mainloop; unroll-8 lets ptxas front-batch up to 16 LDG.128s per group
    #pragma unroll 8
    for (int k = 0; k < NITER; k++) {
        float4 av = ldcs4(reinterpret_cast<const float4*>(zrowA + 16 * k));
        float4 bv = ldcs4(reinterpret_cast<const float4*>(zrowB + 16 * k));
        unsigned long long zpa01 = pack2(av.x, av.y);
        unsigned long long zpa23 = pack2(av.z, av.w);
        unsigned long long zpb01 = pack2(bv.x, bv.y);
        unsigned long long zpb23 = pack2(bv.z, bv.w);
        const float* wbase = sWcT + 16 * k + 4 * j;
        #pragma unroll
        for (int d = 0; d < DDIM; d++) {
            ulonglong2 wd = *reinterpret_cast<const ulonglong2*>(wbase + d * C_IN);
            accA[d] = fma2(zpa01, wd.x, accA[d]);
            accA[d] = fma2(zpa23, wd.y, accA[d]);
            accB[d] = fma2(zpb01, wd.x, accB[d]);
            accB[d] = fma2(zpb23, wd.y, accB[d]);
        }
    }

    // Quad reduction; lane j keeps dims 2j, 2j+1 for both tokens
    const int d0 = 2 * j, d1 = 2 * j + 1;
    float zcA0 = 0.f, zcA1 = 0.f, zcB0 = 0.f, zcB1 = 0.f;
    #pragma unroll
    for (int d = 0; d < DDIM; d++) {
        float lo, hi, va, vb;
        unpack2(accA[d], lo, hi); va = lo + hi;
        unpack2(accB[d], lo, hi); vb = lo + hi;
        va += __shfl_xor_sync(0xffffffffu, va, 1);
        va += __shfl_xor_sync(0xffffffffu, va, 2);
        vb += __shfl_xor_sync(0xffffffffu, vb, 1);
        vb += __shfl_xor_sync(0xffffffffu, vb, 2);
        float bcv = sBC[d];
        va += bcv; vb += bcv;
        if (d == d0) { zcA0 = va; zcB0 = vb; }
        if (d == d1) { zcA1 = va; zcB1 = vb; }
    }

    // Argmax per token (sequential halves bound register pressure)
    float err = 0.0f;
    #pragma unroll
    for (int half = 0; half < 2; half++) {
        const int mtok = half ? tokB : tokA;
        const int lt   = half ? lB : lA;
        const float zv0 = half ? zcB0 : zcA0;
        const float zv1 = half ? zcB1 : zcA1;
        const float4* u4 = reinterpret_cast<const float4*>(
            u + (size_t)lt * (DDIM * LDIM) + 16 * j);
        float4 ua = ldcs4(u4 + 0), ub = ldcs4(u4 + 1);
        float4 uc = ldcs4(u4 + 2), ud = ldcs4(u4 + 3);
        float uv0[LDIM] = {ua.x, ua.y, ua.z, ua.w, ub.x, ub.y, ub.z, ub.w};
        float uv1[LDIM] = {uc.x, uc.y, uc.z, uc.w, ud.x, ud.y, ud.z, ud.w};

        // argmax_l of gumbel(u) - |zc - cb| (== reference softmax argmax,
        // TAU=1; strict > keeps first index on ties, matching jnp.argmax)
        float best0 = -INFINITY, best1 = -INFINITY;
        float code0 = 0.f, code1 = 0.f;
        #pragma unroll
        for (int l = 0; l < LDIM; l++) {
            float cbv0 = sCB[d0 * LDIM + l];
            float cbv1 = sCB[d1 * LDIM + l];
            float g0 = -logf(-logf(uv0[l] + 1e-10f));
            float g1 = -logf(-logf(uv1[l] + 1e-10f));
            float s0 = g0 - fabsf(zv0 - cbv0);
            float s1 = g1 - fabsf(zv1 - cbv1);
            if (s0 > best0) { best0 = s0; code0 = cbv0; }
            if (s1 > best1) { best1 = s1; code1 = cbv1; }
        }
        if (mtok < ntok) {
            float e0 = zv0 - code0, e1 = zv1 - code1;
            err += e0 * e0 + e1 * e1;
        }
        ulonglong2 cw;
        cw.x = pack2(code0, code0);
        cw.y = pack2(code1, code1);
        *reinterpret_cast<ulonglong2*>(
            &sC[(trow + half * HALF) * DDIM + d0]) = cw;
    }

    // Block-reduce squared error -> per-block partial
    #pragma unroll
    for (int o = 16; o > 0; o >>= 1) err += __shfl_down_sync(0xffffffffu, err, o);
    if ((tid & 31) == 0) sRed[tid >> 5] = err;
    __syncthreads();   // also publishes sC for phase 2
    if (tid == 0) {
        float t = 0.f;
        #pragma unroll
        for (int w = 0; w < THREADS / 32; w++) t += sRed[w];
        g_partials[blockIdx.x] = t;
    }

    // ---------------- Phase 2: expand ----------------
    if (tid < EXP_THREADS) {
        const int c0 = tid * 4;
        ulonglong2 wv[DDIM];
        #pragma unroll
        for (int d = 0; d < DDIM; d++)
            wv[d] = *reinterpret_cast<const ulonglong2*>(&We[d * C_IN + c0]);
        ulonglong2 bev = *reinterpret_cast<const ulonglong2*>(&be[c0]);

        const int tok0 = blockIdx.x * TILE;
        int tmax = ntok - tok0;
        if (tmax > TILE) tmax = TILE;

        int t = 0;
        for (; t + 4 <= tmax; t += 4) {
            unsigned long long a[4][2];
            #pragma unroll
            for (int q = 0; q < 4; q++) { a[q][0] = bev.x; a[q][1] = bev.y; }
            #pragma unroll
            for (int d = 0; d < DDIM; d++) {
                #pragma unroll
                for (int q = 0; q < 4; q++) {
                    unsigned long long cd = sC[(t + q) * DDIM + d];  // broadcast
                    a[q][0] = fma2(cd, wv[d].x, a[q][0]);
                    a[q][1] = fma2(cd, wv[d].y, a[q][1]);
                }
            }
            #pragma unroll
            for (int q = 0; q < 4; q++) {
                float4 ov;
                unpack2(a[q][0], ov.x, ov.y);
                unpack2(a[q][1], ov.z, ov.w);
                stcs4(reinterpret_cast<float4*>(
                          &out[(size_t)(tok0 + t + q) * C_IN + c0]), ov);
            }
        }
        for (; t < tmax; t++) {
            unsigned long long s0 = bev.x, s1 = bev.y;
            #pragma unroll
            for (int d = 0; d < DDIM; d++) {
                unsigned long long cd = sC[t * DDIM + d];
                s0 = fma2(cd, wv[d].x, s0);
                s1 = fma2(cd, wv[d].y, s1);
            }
            float4 ov;
            unpack2(s0, ov.x, ov.y);
            unpack2(s1, ov.z, ov.w);
            stcs4(reinterpret_cast<float4*>(
                      &out[(size_t)(tok0 + t) * C_IN + c0]), ov);
        }
    }

    // ---------------- Tail: last block finalizes the error scalar ----------
    if (erridx >= 0) {
        if (tid == 0) {
            __threadfence();  // publish g_partials[bid] before counting
            // wraps to 0 after nblk increments -> self-resetting across replays
            sLast = (atomicInc(&g_done, (unsigned)nblk - 1u) == (unsigned)nblk - 1u);
        }
        __syncthreads();
        if (sLast) {
            float s = 0.f;
            for (int i = tid; i < nblk; i += THREADS) s += g_partials[i];
            #pragma unroll
            for (int o = 16; o > 0; o >>= 1)
                s += __shfl_down_sync(0xffffffffu, s, o);
            if ((tid & 31) == 0) sRed[tid >> 5] = s;
            __syncthreads();
            if (tid == 0) {
                float tot = 0.f;
                #pragma unroll
                for (int w = 0; w < THREADS / 32; w++) tot += sRed[w];
                out[erridx] = tot * errinv;
            }
        }
    }
}

extern "C" void kernel_launch(void* const* d_in, const int* in_sizes, int n_in,
                              void* d_out, int out_size) {
    const float* z  = (const float*)d_in[0];
    const float* u  = (const float*)d_in[1];
    const float* Wc = (const float*)d_in[2];
    const float* bc = (const float*)d_in[3];
    const float* We = (const float*)d_in[4];
    const float* be = (const float*)d_in[5];
    const float* cb = (const float*)d_in[6];
    // d_in[7] = codebook_mask: all-true here (levels == [8]*8), intentionally unused.
    float* out = (float*)d_out;

    const int ntok = in_sizes[0] / C_IN;            // 65536
    const int nblk = (ntok + TILE - 1) / TILE;      // 512

    long long erridx = (out_size > ntok * C_IN) ? (long long)ntok * C_IN : -1;

    k_fused<<<nblk, THREADS>>>(z, u, Wc, bc, We, be, cb, out, ntok, nblk,
                               erridx, 1.0f / ((float)ntok * (float)DDIM));
}

// round 17
// speedup vs baseline: 1.1112x; 1.0013x over previous
#include <cuda_runtime.h>
#include <math.h>

#define C_IN 768
#define DDIM 8
#define LDIM 8

#define THREADS 256
#define TILE 128                // tokens per block; warp handles 16 (8 A + 8 B)
#define NITER2 (C_IN / 32)      // 24 double-chunks (32 floats = one 128B line)
#define EXP_THREADS 192         // phase-2 channel owners (192*4 = 768)

// Scratch (no allocations allowed)
__device__ float g_partials[2048];
__device__ unsigned int g_done = 0;   // self-resetting via atomicInc wrap

static __device__ __forceinline__ unsigned long long pack2(float lo, float hi) {
    unsigned long long r;
    asm("mov.b64 %0, {%1, %2};" : "=l"(r) : "f"(lo), "f"(hi));
    return r;
}
static __device__ __forceinline__ void unpack2(unsigned long long v, float& lo, float& hi) {
    asm("mov.b64 {%0, %1}, %2;" : "=f"(lo), "=f"(hi) : "l"(v));
}
// Packed fp32x2 FMA (sm_100+): 2 IEEE fp32 FMAs per instruction.
static __device__ __forceinline__ unsigned long long fma2(unsigned long long a,
                                                          unsigned long long b,
                                                          unsigned long long c) {
    unsigned long long d;
    asm("fma.rn.f32x2 %0, %1, %2, %3;" : "=l"(d) : "l"(a), "l"(b), "l"(c));
    return d;
}
// Streaming (evict-first) 128-bit load/store for read-once / write-once data.
static __device__ __forceinline__ float4 ldcs4(const float4* p) {
    float4 v;
    asm volatile("ld.global.cs.v4.f32 {%0,%1,%2,%3}, [%4];"
                 : "=f"(v.x), "=f"(v.y), "=f"(v.z), "=f"(v.w) : "l"(p));
    return v;
}
static __device__ __forceinline__ void stcs4(float4* p, float4 v) {
    asm volatile("st.global.cs.v4.f32 [%0], {%1,%2,%3,%4};"
                 :: "l"(p), "f"(v.x), "f"(v.y), "f"(v.z), "f"(v.w) : "memory");
}

// Fused kernel:
//   Phase 1: compress GEMV with full-line z loads (8 consecutive lanes cover
//            one token's 128B chunk -> 4 L1 wavefronts per LDG instead of 8)
//            and 4 tokens per lane in scalar f32 accumulators. One weight
//            LDS.128 per dim per double-chunk feeds 16 FFMA (4 tokens).
//            Oct-reduction; lane o owns dim o of its 4 tokens. Gumbel argmax;
//            codes -> shared, error partial -> global.
//   Phase 2: expand z_q = codes @ We + be from shared (2 dims per LDS.128),
//            coalesced STG.128.
//   Tail:    deterministic last-block reduction of error partials.
__global__ void __launch_bounds__(THREADS, 4) k_fused(
    const float* __restrict__ z, const float* __restrict__ u,
    const float* __restrict__ Wc, const float* __restrict__ bc,
    const float* __restrict__ We, const float* __restrict__ be,
    const float* __restrict__ cb,
    float* __restrict__ out, int ntok, int nblk,
    long long erridx, float errinv)
{
    __shared__ __align__(128) float sWcT[DDIM * C_IN];           // 24 KB transposed
    __shared__ __align__(16) unsigned long long sC[TILE * DDIM]; // 8 KB (code,code)
    __shared__ float sBC[DDIM];
    __shared__ float sCB[DDIM * LDIM];
    __shared__ float sRed[THREADS / 32];
    __shared__ unsigned int sLast;

    const int tid = threadIdx.x;

    // Stage transposed compress weights (coalesced global reads)
    for (int i = tid; i < C_IN * DDIM; i += THREADS) {
        int c = i >> 3, d = i & 7;
        sWcT[d * C_IN + c] = Wc[i];
    }
    if (tid < DDIM) sBC[tid] = bc[tid];
    if (tid < DDIM * LDIM) sCB[tid] = cb[tid];
    __syncthreads();

    // ---------------- Phase 1: compress (4 tokens per lane) ----------------
    const int w    = tid >> 5;                  // warp 0..7
    const int lane = tid & 31;
    const int g    = lane >> 3;                 // token subgroup 0..3
    const int o    = lane & 7;                  // position in oct (dim owner)
    const int tok0 = blockIdx.x * TILE;

    // Lane's 4 local tokens: lA0, lA0+4 (A set), +64, +68 (B set)
    const int lA0 = w * 8 + g;                  // 0..59
    int ltok[4] = {lA0, lA0 + 4, lA0 + 64, lA0 + 68};

    const float* pz[4];
    #pragma unroll
    for (int t = 0; t < 4; t++) {
        int gt = tok0 + ltok[t];
        int rt = (gt < ntok) ? gt : (ntok - 1);
        pz[t] = z + (size_t)rt * C_IN + 4 * o;
    }

    float acc[4][DDIM];
    #pragma unroll
    for (int t = 0; t < 4; t++)
        #pragma unroll
        for (int d = 0; d < DDIM; d++) acc[t][d] = 0.0f;

    // Mainloop: 4 LDG.128 (full-line, 4 wf each) + 8 LDS.128 + 128 FFMA
    #pragma unroll 1
    for (int k = 0; k < NITER2; k++) {
        float4 zv0 = ldcs4(reinterpret_cast<const float4*>(pz[0] + 32 * k));
        float4 zv1 = ldcs4(reinterpret_cast<const float4*>(pz[1] + 32 * k));
        float4 zv2 = ldcs4(reinterpret_cast<const float4*>(pz[2] + 32 * k));
        float4 zv3 = ldcs4(reinterpret_cast<const float4*>(pz[3] + 32 * k));
        const float* wb = sWcT + 32 * k + 4 * o;
        #pragma unroll
        for (int d = 0; d < DDIM; d++) {
            float4 w4 = *reinterpret_cast<const float4*>(wb + d * C_IN);
            acc[0][d] = fmaf(zv0.w, w4.w, fmaf(zv0.z, w4.z,
                        fmaf(zv0.y, w4.y, fmaf(zv0.x, w4.x, acc[0][d]))));
            acc[1][d] = fmaf(zv1.w, w4.w, fmaf(zv1.z, w4.z,
                        fmaf(zv1.y, w4.y, fmaf(zv1.x, w4.x, acc[1][d]))));
            acc[2][d] = fmaf(zv2.w, w4.w, fmaf(zv2.z, w4.z,
                        fmaf(zv2.y, w4.y, fmaf(zv2.x, w4.x, acc[2][d]))));
            acc[3][d] = fmaf(zv3.w, w4.w, fmaf(zv3.z, w4.z,
                        fmaf(zv3.y, w4.y, fmaf(zv3.x, w4.x, acc[3][d]))));
        }
    }

    // Oct reduction (xor 1,2,4 stay within the oct); lane o keeps dim o
    float zc[4];
    #pragma unroll
    for (int d = 0; d < DDIM; d++) {
        #pragma unroll
        for (int t = 0; t < 4; t++) {
            float v = acc[t][d];
            v += __shfl_xor_sync(0xffffffffu, v, 1);
            v += __shfl_xor_sync(0xffffffffu, v, 2);
            v += __shfl_xor_sync(0xffffffffu, v, 4);
            if (d == o) zc[t] = v + sBC[d];
        }
    }

    // Argmax per token for dim o; codes -> shared, error accumulated
    float err = 0.0f;
    #pragma unroll
    for (int t = 0; t < 4; t++) {
        const int gt = tok0 + ltok[t];
        const int rt = (gt < ntok) ? gt : (ntok - 1);
        const float4* u4 = reinterpret_cast<const float4*>(
            u + (size_t)rt * (DDIM * LDIM) + 8 * o);
        float4 ua = ldcs4(u4 + 0), ub = ldcs4(u4 + 1);
        float uv[LDIM] = {ua.x, ua.y, ua.z, ua.w, ub.x, ub.y, ub.z, ub.w};

        // argmax_l of gumbel(u) - |zc - cb| (== reference softmax argmax,
        // TAU=1; strict > keeps first index on ties, matching jnp.argmax)
        float best = -INFINITY, code = 0.f;
        const float zv = zc[t];
        #pragma unroll
        for (int l = 0; l < LDIM; l++) {
            float cbv = sCB[o * LDIM + l];
            float gmb = -logf(-logf(uv[l] + 1e-10f));
            float s = gmb - fabsf(zv - cbv);
            if (s > best) { best = s; code = cbv; }
        }
        if (gt < ntok) {
            float e = zv - code;
            err += e * e;
        }
        sC[ltok[t] * DDIM + o] = pack2(code, code);
    }

    // Block-reduce squared error -> per-block partial
    #pragma unroll
    for (int s = 16; s > 0; s >>= 1) err += __shfl_down_sync(0xffffffffu, err, s);
    if ((tid & 31) == 0) sRed[tid >> 5] = err;
    __syncthreads();   // also publishes sC for phase 2
    if (tid == 0) {
        float t = 0.f;
        #pragma unroll
        for (int v = 0; v < THREADS / 32; v++) t += sRed[v];
        g_partials[blockIdx.x] = t;
    }

    // ---------------- Phase 2: expand ----------------
    if (tid < EXP_THREADS) {
        const int c0 = tid * 4;
        ulonglong2 wv[DDIM];
        #pragma unroll
        for (int d = 0; d < DDIM; d++)
            wv[d] = *reinterpret_cast<const ulonglong2*>(&We[d * C_IN + c0]);
        ulonglong2 bev = *reinterpret_cast<const ulonglong2*>(&be[c0]);

        int tmax = ntok - tok0;
        if (tmax > TILE) tmax = TILE;

        int t = 0;
        for (; t + 4 <= tmax; t += 4) {
            unsigned long long a[4][2];
            #pragma unroll
            for (int q = 0; q < 4; q++) { a[q][0] = bev.x; a[q][1] = bev.y; }
            #pragma unroll
            for (int d = 0; d < DDIM; d += 2) {
                #pragma unroll
                for (int q = 0; q < 4; q++) {
                    // one LDS.128 delivers the dup'd codes of dims d, d+1
                    ulonglong2 cp = *reinterpret_cast<const ulonglong2*>(
                        &sC[(t + q) * DDIM + d]);
                    a[q][0] = fma2(cp.x, wv[d].x, a[q][0]);
                    a[q][1] = fma2(cp.x, wv[d].y, a[q][1]);
                    a[q][0] = fma2(cp.y, wv[d + 1].x, a[q][0]);
                    a[q][1] = fma2(cp.y, wv[d + 1].y, a[q][1]);
                }
            }
            #pragma unroll
            for (int q = 0; q < 4; q++) {
                float4 ov;
                unpack2(a[q][0], ov.x, ov.y);
                unpack2(a[q][1], ov.z, ov.w);
                stcs4(reinterpret_cast<float4*>(
                          &out[(size_t)(tok0 + t + q) * C_IN + c0]), ov);
            }
        }
        for (; t < tmax; t++) {
            unsigned long long s0 = bev.x, s1 = bev.y;
            #pragma unroll
            for (int d = 0; d < DDIM; d += 2) {
                ulonglong2 cp = *reinterpret_cast<const ulonglong2*>(
                    &sC[t * DDIM + d]);
                s0 = fma2(cp.x, wv[d].x, s0);
                s1 = fma2(cp.x, wv[d].y, s1);
                s0 = fma2(cp.y, wv[d + 1].x, s0);
                s1 = fma2(cp.y, wv[d + 1].y, s1);
            }
            float4 ov;
            unpack2(s0, ov.x, ov.y);
            unpack2(s1, ov.z, ov.w);
            stcs4(reinterpret_cast<float4*>(
                      &out[(size_t)(tok0 + t) * C_IN + c0]), ov);
        }
    }

    // ---------------- Tail: last block finalizes the error scalar ----------
    if (erridx >= 0) {
        if (tid == 0) {
            __threadfence();  // publish g_partials[bid] before counting
            // wraps to 0 after nblk increments -> self-resetting across replays
            sLast = (atomicInc(&g_done, (unsigned)nblk - 1u) == (unsigned)nblk - 1u);
        }
        __syncthreads();
        if (sLast) {
            float s = 0.f;
            for (int i = tid; i < nblk; i += THREADS) s += g_partials[i];
            #pragma unroll
            for (int v = 16; v > 0; v >>= 1)
                s += __shfl_down_sync(0xffffffffu, s, v);
            if ((tid & 31) == 0) sRed[tid >> 5] = s;
            __syncthreads();
            if (tid == 0) {
                float tot = 0.f;
                #pragma unroll
                for (int v = 0; v < THREADS / 32; v++) tot += sRed[v];
                out[erridx] = tot * errinv;
            }
        }
    }
}

extern "C" void kernel_launch(void* const* d_in, const int* in_sizes, int n_in,
                              void* d_out, int out_size) {
    const float* z  = (const float*)d_in[0];
    const float* u  = (const float*)d_in[1];
    const float* Wc = (const float*)d_in[2];
    const float* bc = (const float*)d_in[3];
    const float* We = (const float*)d_in[4];
    const float* be = (const float*)d_in[5];
    const float* cb = (const float*)d_in[6];
    // d_in[7] = codebook_mask: all-true here (levels == [8]*8), intentionally unused.
    float* out = (float*)d_out;

    const int ntok = in_sizes[0] / C_IN;            // 65536
    const int nblk = (ntok + TILE - 1) / TILE;      // 512

    long long erridx = (out_size > ntok * C_IN) ? (long long)ntok * C_IN : -1;

    k_fused<<<nblk, THREADS>>>(z, u, Wc, bc, We, be, cb, out, ntok, nblk,
                               erridx, 1.0f / ((float)ntok * (float)DDIM));
}